// round 8
// baseline (speedup 1.0000x reference)
#include <cuda_runtime.h>
#include <cuda_bf16.h>
#include <stdint.h>
#include <math.h>

#define NB 4
#define NS 2048
#define NE 1024
#define ND 128
#define NTOK 8192

typedef __nv_bfloat16 bf;

// ---------------- device scratch (allocation-free) ----------------
__device__ float g_s [(size_t)NTOK * NS];            // 64 MB scores
__device__ bf g_Ph[(size_t)NTOK * NS];
__device__ bf g_Pl[(size_t)NTOK * NS];
__device__ bf g_xh[NTOK * NE], g_xl[NTOK * NE];      // split x
__device__ bf g_qh[NTOK * ND], g_ql[NTOK * ND];
__device__ bf g_kh[NTOK * ND], g_kl[NTOK * ND];
__device__ bf g_vh[NTOK * ND], g_vl[NTOK * ND];      // [tok][d]
__device__ bf g_wh[3 * NE * ND], g_wl[3 * NE * ND];  // [mat][e][d]

// ---------------- helpers ----------------
__device__ __forceinline__ uint32_t s2u(const void* p) {
    uint32_t a;
    asm("{ .reg .u64 t; cvta.to.shared.u64 t, %1; cvt.u32.u64 %0, t; }" : "=r"(a) : "l"(p));
    return a;
}
__device__ __forceinline__ void ldsm4(uint32_t& r0, uint32_t& r1, uint32_t& r2, uint32_t& r3, uint32_t a) {
    asm volatile("ldmatrix.sync.aligned.m8n8.x4.shared.b16 {%0,%1,%2,%3}, [%4];"
        : "=r"(r0), "=r"(r1), "=r"(r2), "=r"(r3) : "r"(a));
}
__device__ __forceinline__ void ldsm4t(uint32_t& r0, uint32_t& r1, uint32_t& r2, uint32_t& r3, uint32_t a) {
    asm volatile("ldmatrix.sync.aligned.m8n8.x4.trans.shared.b16 {%0,%1,%2,%3}, [%4];"
        : "=r"(r0), "=r"(r1), "=r"(r2), "=r"(r3) : "r"(a));
}
__device__ __forceinline__ void mma16816(float* c,
    uint32_t a0, uint32_t a1, uint32_t a2, uint32_t a3, uint32_t b0, uint32_t b1) {
    asm volatile("mma.sync.aligned.m16n8k16.row.col.f32.bf16.bf16.f32 "
        "{%0,%1,%2,%3}, {%4,%5,%6,%7}, {%8,%9}, {%0,%1,%2,%3};"
        : "+f"(c[0]), "+f"(c[1]), "+f"(c[2]), "+f"(c[3])
        : "r"(a0), "r"(a1), "r"(a2), "r"(a3), "r"(b0), "r"(b1));
}
__device__ __forceinline__ void cpa16(uint32_t s, const void* g) {
    asm volatile("cp.async.cg.shared.global [%0], [%1], 16;" :: "r"(s), "l"(g) : "memory");
}
__device__ __forceinline__ void cpa_commit() {
    asm volatile("cp.async.commit_group;" ::: "memory");
}
template<int N> __device__ __forceinline__ void cpa_wait() {
    asm volatile("cp.async.wait_group %0;" :: "n"(N) : "memory");
}
__device__ __forceinline__ void split2(float a, float b, uint32_t& hi, uint32_t& lo) {
    bf ha = __float2bfloat16(a), hb = __float2bfloat16(b);
    bf la = __float2bfloat16(a - __bfloat162float(ha));
    bf lb = __float2bfloat16(b - __bfloat162float(hb));
    __nv_bfloat162 H, L;
    H.x = ha; H.y = hb; L.x = la; L.y = lb;
    hi = *(uint32_t*)&H; lo = *(uint32_t*)&L;
}
__device__ __forceinline__ void tri_decode(int bidx, int& bi, int& bj) {
    int r = (int)((sqrtf(8.f * bidx + 1.f) - 1.f) * 0.5f);
    while ((r + 1) * (r + 2) / 2 <= bidx) r++;
    while (r * (r + 1) / 2 > bidx) r--;
    bi = r; bj = bidx - r * (r + 1) / 2;
}

// Warp-level split-bf16 GEMM over a K=32 span starting at k0 (elements).
// ILP-optimized: all fragments preloaded, MMAs issued in 3 passes by product
// type (hh, hl, lh) so each accumulator's reuse distance is 8+ independent MMAs.
template<int MW, int AS, int BS, int TRANSB>
__device__ __forceinline__ void compute32(float (*acc)[4],
    uint32_t Ah, uint32_t Al, uint32_t Bh, uint32_t Bl,
    int k0, int lane, int warpM, int warpN)
{
    const uint32_t arow = warpM * (MW * 16) + (lane & 15);
    #pragma unroll
    for (int ks = 0; ks < 2; ks++) {
        uint32_t ah[MW][4], al[MW][4];
        #pragma unroll
        for (int m = 0; m < MW; m++) {
            uint32_t off = ((arow + m * 16) * AS + k0 + ks * 16 + ((lane >> 4) & 1) * 8) * 2;
            ldsm4(ah[m][0], ah[m][1], ah[m][2], ah[m][3], Ah + off);
            ldsm4(al[m][0], al[m][1], al[m][2], al[m][3], Al + off);
        }
        uint32_t bh[4][4], bl[4][4];
        #pragma unroll
        for (int p = 0; p < 4; p++) {
            if (TRANSB) {
                uint32_t off = ((uint32_t)(k0 + ks * 16 + (lane & 15)) * BS
                              + warpN * 64 + p * 16 + ((lane >> 4) & 1) * 8) * 2;
                ldsm4t(bh[p][0], bh[p][1], bh[p][2], bh[p][3], Bh + off);
                ldsm4t(bl[p][0], bl[p][1], bl[p][2], bl[p][3], Bl + off);
            } else {
                uint32_t off = ((uint32_t)(warpN * 64 + p * 16 + (lane & 7) + ((lane >> 4) & 1) * 8) * BS
                              + k0 + ks * 16 + ((lane >> 3) & 1) * 8) * 2;
                ldsm4(bh[p][0], bh[p][1], bh[p][2], bh[p][3], Bh + off);
                ldsm4(bl[p][0], bl[p][1], bl[p][2], bl[p][3], Bl + off);
            }
        }
        // pass 1: hi * hi
        #pragma unroll
        for (int p = 0; p < 4; p++)
            #pragma unroll
            for (int m = 0; m < MW; m++) {
                mma16816(acc[m * 8 + 2 * p],     ah[m][0], ah[m][1], ah[m][2], ah[m][3], bh[p][0], bh[p][1]);
                mma16816(acc[m * 8 + 2 * p + 1], ah[m][0], ah[m][1], ah[m][2], ah[m][3], bh[p][2], bh[p][3]);
            }
        // pass 2: hi * lo
        #pragma unroll
        for (int p = 0; p < 4; p++)
            #pragma unroll
            for (int m = 0; m < MW; m++) {
                mma16816(acc[m * 8 + 2 * p],     ah[m][0], ah[m][1], ah[m][2], ah[m][3], bl[p][0], bl[p][1]);
                mma16816(acc[m * 8 + 2 * p + 1], ah[m][0], ah[m][1], ah[m][2], ah[m][3], bl[p][2], bl[p][3]);
            }
        // pass 3: lo * hi
        #pragma unroll
        for (int p = 0; p < 4; p++)
            #pragma unroll
            for (int m = 0; m < MW; m++) {
                mma16816(acc[m * 8 + 2 * p],     al[m][0], al[m][1], al[m][2], al[m][3], bh[p][0], bh[p][1]);
                mma16816(acc[m * 8 + 2 * p + 1], al[m][0], al[m][1], al[m][2], al[m][3], bh[p][2], bh[p][3]);
            }
    }
}

// ---------------- prepass: split x and W ----------------
__global__ __launch_bounds__(256) void xsplit_kernel(const float* __restrict__ x) {
    int i = blockIdx.x * 256 + threadIdx.x;          // float4 index
    float4 v = ((const float4*)x)[i];
    uint32_t h0, l0, h1, l1;
    split2(v.x, v.y, h0, l0);
    split2(v.z, v.w, h1, l1);
    ((uint2*)g_xh)[i] = make_uint2(h0, h1);
    ((uint2*)g_xl)[i] = make_uint2(l0, l1);
}
__global__ __launch_bounds__(256) void wsplit_kernel(const float* __restrict__ wq,
    const float* __restrict__ wk, const float* __restrict__ wv) {
    const float* w = blockIdx.y == 0 ? wq : (blockIdx.y == 1 ? wk : wv);
    int i = blockIdx.x * 256 + threadIdx.x;
    float f = w[i];
    bf h = __float2bfloat16(f);
    bf l = __float2bfloat16(f - __bfloat162float(h));
    size_t o = (size_t)blockIdx.y * NE * ND + i;
    g_wh[o] = h; g_wl[o] = l;
}

// ---------------- kernel 1: QKV projection (M64, cp.async 3-stage) ----------------
#define QKV_STAGE 27648u
__global__ __launch_bounds__(256) void qkv_mma(
    const float* __restrict__ bq, const float* __restrict__ bk, const float* __restrict__ bv)
{
    extern __shared__ __align__(16) char sm[];
    const uint32_t sb = s2u(sm);
    const int tid = threadIdx.x, lane = tid & 31, wid = tid >> 5;
    const int warpM = wid >> 1, warpN = wid & 1;
    const int m0 = blockIdx.x * 64, mat = blockIdx.y;

    float acc[8][4];
    #pragma unroll
    for (int i = 0; i < 8; i++)
        #pragma unroll
        for (int j = 0; j < 4; j++) acc[i][j] = 0.f;

    auto load_stage = [&](int st, int kb) {
        uint32_t stg = sb + st * QKV_STAGE;
        #pragma unroll
        for (int i = 0; i < 2; i++) {                 // A: 64 rows x 4 segs x2
            int sidx = tid + i * 256;
            int split = sidx >> 8, r = (sidx & 255) >> 2, seg = sidx & 3;
            const bf* src = (split ? g_xl : g_xh) + (size_t)(m0 + r) * NE + kb + seg * 8;
            cpa16(stg + split * 5120 + r * 80 + seg * 16, src);
        }
        #pragma unroll
        for (int i = 0; i < 4; i++) {                 // B: 32 rows x 16 segs x2
            int sidx = tid + i * 256;
            int split = sidx >> 9, r = (sidx & 511) >> 4, seg = sidx & 15;
            const bf* src = (split ? g_wl : g_wh) + ((size_t)mat * NE + kb + r) * ND + seg * 8;
            cpa16(stg + 10240 + split * 8704 + r * 272 + seg * 16, src);
        }
        cpa_commit();
    };

    load_stage(0, 0);
    load_stage(1, 32);
    for (int c = 0; c < 32; c++) {
        if (c >= 31) cpa_wait<0>(); else cpa_wait<1>();
        __syncthreads();
        uint32_t stg = sb + (uint32_t)(c % 3) * QKV_STAGE;
        compute32<1, 40, 136, 1>(acc, stg, stg + 5120, stg + 10240, stg + 10240 + 8704,
                                 0, lane, warpM, warpN);
        if (c + 2 < 32) load_stage((c + 2) % 3, (c + 2) * 32);
    }

    const float* bias = mat == 0 ? bq : (mat == 1 ? bk : bv);
    bf* oh = mat == 0 ? g_qh : (mat == 1 ? g_kh : g_vh);
    bf* ol = mat == 0 ? g_ql : (mat == 1 ? g_kl : g_vl);
    const int row = m0 + warpM * 16 + (lane >> 2);
    #pragma unroll
    for (int n = 0; n < 8; n++) {
        int col = warpN * 64 + n * 8 + 2 * (lane & 3);
        float b0 = __ldg(bias + col), b1 = __ldg(bias + col + 1);
        uint32_t H, L;
        split2(acc[n][0] + b0, acc[n][1] + b1, H, L);
        *(uint32_t*)(oh + (size_t)row * ND + col) = H;
        *(uint32_t*)(ol + (size_t)row * ND + col) = L;
        split2(acc[n][2] + b0, acc[n][3] + b1, H, L);
        *(uint32_t*)(oh + (size_t)(row + 8) * ND + col) = H;
        *(uint32_t*)(ol + (size_t)(row + 8) * ND + col) = L;
    }
}

// ---------------- kernel 2: scores (M64, full-K resident, 2 async groups) ----------------
__global__ __launch_bounds__(256) void scores_mma()
{
    extern __shared__ __align__(16) char sm[];
    const uint32_t sb = s2u(sm);
    const int tid = threadIdx.x, lane = tid & 31, wid = tid >> 5;
    const int warpM = wid >> 1, warpN = wid & 1;
    int bi, bj; tri_decode(blockIdx.x, bi, bj);
    const int b = blockIdx.y, i0 = bi * 128 + blockIdx.z * 64, j0 = bj * 128;

    float acc[8][4];
    #pragma unroll
    for (int i = 0; i < 8; i++)
        #pragma unroll
        for (int j = 0; j < 4; j++) acc[i][j] = 0.f;

    const size_t qbase = (size_t)(b * NS + i0) * ND;
    const size_t kbase = (size_t)(b * NS + j0) * ND;

    auto load_group = [&](int kb) {
        #pragma unroll
        for (int i = 0; i < 4; i++) {                 // A: 64 rows x 8 segs x2
            int sidx = tid + i * 256;
            int split = sidx >> 9, r = (sidx & 511) >> 3, seg = sidx & 7;
            const bf* src = (split ? g_ql : g_qh) + qbase + (size_t)r * ND + kb + seg * 8;
            cpa16(sb + split * 17408 + r * 272 + (kb + seg * 8) * 2, src);
        }
        #pragma unroll
        for (int i = 0; i < 8; i++) {                 // B: 128 rows x 8 segs x2
            int sidx = tid + i * 256;
            int split = sidx >> 10, r = (sidx & 1023) >> 3, seg = sidx & 7;
            const bf* src = (split ? g_kl : g_kh) + kbase + (size_t)r * ND + kb + seg * 8;
            cpa16(sb + 34816 + split * 34816 + r * 272 + (kb + seg * 8) * 2, src);
        }
        cpa_commit();
    };
    load_group(0);
    load_group(64);
    cpa_wait<1>(); __syncthreads();
    compute32<1, 136, 136, 0>(acc, sb, sb + 17408, sb + 34816, sb + 69632,  0, lane, warpM, warpN);
    compute32<1, 136, 136, 0>(acc, sb, sb + 17408, sb + 34816, sb + 69632, 32, lane, warpM, warpN);
    cpa_wait<0>(); __syncthreads();
    compute32<1, 136, 136, 0>(acc, sb, sb + 17408, sb + 34816, sb + 69632, 64, lane, warpM, warpN);
    compute32<1, 136, 136, 0>(acc, sb, sb + 17408, sb + 34816, sb + 69632, 96, lane, warpM, warpN);

    float* sout = g_s + ((size_t)b << 22);
    const float scale = 0.08838834764831845f;
    const int gi = i0 + warpM * 16 + (lane >> 2);
    #pragma unroll
    for (int n = 0; n < 8; n++) {
        int gj = j0 + warpN * 64 + n * 8 + 2 * (lane & 3);
        float2 v0, v1;
        v0.x = (gj     <= gi) ? acc[n][0] * scale : -INFINITY;
        v0.y = (gj + 1 <= gi) ? acc[n][1] * scale : -INFINITY;
        v1.x = (gj     <= gi + 8) ? acc[n][2] * scale : -INFINITY;
        v1.y = (gj + 1 <= gi + 8) ? acc[n][3] * scale : -INFINITY;
        *(float2*)(sout + (size_t)gi * NS + gj) = v0;
        *(float2*)(sout + (size_t)(gi + 8) * NS + gj) = v1;
    }
}

// ---------------- kernel 3: softmax -> split-bf16 P (vectorized) ----------------
__global__ __launch_bounds__(256) void softmax_kernel() {
    __shared__ __align__(16) float buf[2048];
    __shared__ float red[8];
    const int rrow = blockIdx.x;
    const int b = rrow >> 11, i = rrow & 2047;
    const float4* s4 = (const float4*)(g_s + ((size_t)b << 22) + (size_t)i * NS);
    const int n4 = (((i >> 7) + 1) << 7) >> 2;        // Lp/4
    const int tid = threadIdx.x, lane = tid & 31, wid = tid >> 5;
    float4* b4 = (float4*)buf;

    float m = -INFINITY;
    for (int j = tid; j < n4; j += 256) {
        float4 v = s4[j]; b4[j] = v;
        m = fmaxf(m, fmaxf(fmaxf(v.x, v.y), fmaxf(v.z, v.w)));
    }
    #pragma unroll
    for (int o = 16; o; o >>= 1) m = fmaxf(m, __shfl_xor_sync(0xffffffffu, m, o));
    if (lane == 0) red[wid] = m;
    __syncthreads();
    m = red[0];
    #pragma unroll
    for (int w = 1; w < 8; w++) m = fmaxf(m, red[w]);
    __syncthreads();

    float sum = 0.f;
    for (int j = tid; j < n4; j += 256) {
        float4 v = b4[j];
        v.x = __expf(v.x - m); v.y = __expf(v.y - m);
        v.z = __expf(v.z - m); v.w = __expf(v.w - m);
        b4[j] = v;
        sum += (v.x + v.y) + (v.z + v.w);
    }
    #pragma unroll
    for (int o = 16; o; o >>= 1) sum += __shfl_xor_sync(0xffffffffu, sum, o);
    if (lane == 0) red[wid] = sum;
    __syncthreads();
    sum = red[0];
    #pragma unroll
    for (int w = 1; w < 8; w++) sum += red[w];

    const float inv = 1.f / sum;
    uint2* ph = (uint2*)(g_Ph + (size_t)rrow * NS);
    uint2* pl = (uint2*)(g_Pl + (size_t)rrow * NS);
    for (int j = tid; j < n4; j += 256) {
        float4 v = b4[j];
        uint32_t h0, l0, h1, l1;
        split2(v.x * inv, v.y * inv, h0, l0);
        split2(v.z * inv, v.w * inv, h1, l1);
        ph[j] = make_uint2(h0, h1);
        pl[j] = make_uint2(l0, l1);
    }
}

// ---------------- kernel 4: P.V (M64, full-K resident, 2 async groups) ----------------
__global__ __launch_bounds__(256) void pv_mma(float* __restrict__ out)
{
    extern __shared__ __align__(16) char sm[];
    const uint32_t sb = s2u(sm);
    const int tid = threadIdx.x, lane = tid & 31, wid = tid >> 5;
    const int warpM = wid >> 1, warpN = wid & 1;
    int bi, bj; tri_decode(blockIdx.x, bi, bj);
    const int b = blockIdx.y, i0 = bi * 128 + blockIdx.z * 64, j0 = bj * 128;

    float acc[8][4];
    #pragma unroll
    for (int i = 0; i < 8; i++)
        #pragma unroll
        for (int j = 0; j < 4; j++) acc[i][j] = 0.f;

    const size_t pbase = (size_t)(b * NS + i0) * NS + j0;
    const size_t vbase = (size_t)(b * NS + j0) * ND;

    auto load_group = [&](int kb) {
        #pragma unroll
        for (int i = 0; i < 4; i++) {                 // A: 64 rows x 8 segs x2
            int sidx = tid + i * 256;
            int split = sidx >> 9, r = (sidx & 511) >> 3, seg = sidx & 7;
            const bf* src = (split ? g_Pl : g_Ph) + pbase + (size_t)r * NS + kb + seg * 8;
            cpa16(sb + split * 17408 + r * 272 + (kb + seg * 8) * 2, src);
        }
        #pragma unroll
        for (int i = 0; i < 8; i++) {                 // B: 64 k-rows x 16 segs x2
            int sidx = tid + i * 256;
            int split = sidx >> 10, r = (sidx & 1023) >> 4, seg = sidx & 15;
            const bf* src = (split ? g_vl : g_vh) + vbase + (size_t)(kb + r) * ND + seg * 8;
            cpa16(sb + 34816 + split * 34816 + (kb + r) * 272 + seg * 16, src);
        }
        cpa_commit();
    };
    load_group(0);
    load_group(64);
    cpa_wait<1>(); __syncthreads();
    compute32<1, 136, 136, 1>(acc, sb, sb + 17408, sb + 34816, sb + 69632,  0, lane, warpM, warpN);
    compute32<1, 136, 136, 1>(acc, sb, sb + 17408, sb + 34816, sb + 69632, 32, lane, warpM, warpN);
    cpa_wait<0>(); __syncthreads();
    compute32<1, 136, 136, 1>(acc, sb, sb + 17408, sb + 34816, sb + 69632, 64, lane, warpM, warpN);
    compute32<1, 136, 136, 1>(acc, sb, sb + 17408, sb + 34816, sb + 69632, 96, lane, warpM, warpN);

    const int gi = i0 + warpM * 16 + (lane >> 2);
    #pragma unroll
    for (int n = 0; n < 8; n++) {
        int gj = warpN * 64 + n * 8 + 2 * (lane & 3);
        float* o0 = out + (size_t)(b * NS + gi) * ND + gj;
        float* o1 = out + (size_t)(b * NS + gi + 8) * ND + gj;
        atomicAdd(o0,     acc[n][0]);
        atomicAdd(o0 + 1, acc[n][1]);
        atomicAdd(o1,     acc[n][2]);
        atomicAdd(o1 + 1, acc[n][3]);
    }
}

// ---------------- launch ----------------
extern "C" void kernel_launch(void* const* d_in, const int* in_sizes, int n_in,
                              void* d_out, int out_size) {
    const float* x  = (const float*)d_in[0];
    const float* wq = (const float*)d_in[1];
    const float* bq = (const float*)d_in[2];
    const float* wk = (const float*)d_in[3];
    const float* bk = (const float*)d_in[4];
    const float* wv = (const float*)d_in[5];
    const float* bv = (const float*)d_in[6];
    float* out = (float*)d_out;

    static int inited = 0;
    if (!inited) {
        cudaFuncSetAttribute(qkv_mma,    cudaFuncAttributeMaxDynamicSharedMemorySize, 3 * QKV_STAGE);
        cudaFuncSetAttribute(scores_mma, cudaFuncAttributeMaxDynamicSharedMemorySize, 104448);
        cudaFuncSetAttribute(pv_mma,     cudaFuncAttributeMaxDynamicSharedMemorySize, 104448);
        inited = 1;
    }

    cudaMemsetAsync(out, 0, (size_t)out_size * sizeof(float));
    xsplit_kernel<<<NTOK * NE / 1024, 256>>>(x);
    wsplit_kernel<<<dim3(NE * ND / 256, 3), 256>>>(wq, wk, wv);
    qkv_mma<<<dim3(128, 3), 256, 3 * QKV_STAGE>>>(bq, bk, bv);
    scores_mma<<<dim3(136, NB, 2), 256, 104448>>>();
    softmax_kernel<<<NB * NS, 256>>>();
    pv_mma<<<dim3(136, NB, 2), 256, 104448>>>(out);
}